// round 10
// baseline (speedup 1.0000x reference)
#include <cuda_runtime.h>
#include <math.h>
#include <stdint.h>

#define Bb 2
#define Dd 512
#define Cc 512
#define Tt 32
#define TDIMv 1024
#define Hh 8
#define Fv 64
#define NG 32
#define GA 4

// ---------------- scratch (device globals; no allocation allowed) ----------------
__device__ float g_stats[Bb*Dd*NG*2];
__device__ float g_xt[(size_t)Bb*Dd*Tt*Cc];                 // normalized x, [B,D,T,C]
__device__ float g_time[3*Bb*Tt*Cc];                        // [p,b,t,C]
__device__ float g_E[(size_t)3*Bb*Tt*Tt*Cc];                // silu(emb), [p,b,t,s,C]
__device__ float g_R[(size_t)3*Bb*Tt*Tt*Cc];                // rpe bias [p,b,t,s,C]
__device__ float g_qkv[(size_t)Bb*Dd*Tt*3*Cc];              // [B,D,T,3C]
__device__ float g_attout[(size_t)Bb*Dd*Tt*Cc];             // [B,D,T,C]
__device__ float g_y[(size_t)Bb*Dd*Tt*Cc];                  // [B,D,T,C]

// ---------------- group-norm ----------------
__global__ void gn_stats(const float* __restrict__ x) {
    int bd = blockIdx.x;
    const float4* xp = (const float4*)(x + (size_t)bd * Cc * Tt);
    int warp = threadIdx.x >> 5, lane = threadIdx.x & 31;
    for (int gi = 0; gi < 4; gi++) {
        int g = warp + gi * 8;
        float s = 0.f, ss = 0.f;
        #pragma unroll
        for (int j = 0; j < 4; j++) {
            float4 v = xp[g * 128 + lane + 32 * j];
            s  += v.x + v.y + v.z + v.w;
            ss += v.x * v.x + v.y * v.y + v.z * v.z + v.w * v.w;
        }
        #pragma unroll
        for (int o = 16; o; o >>= 1) {
            s  += __shfl_down_sync(0xffffffffu, s, o);
            ss += __shfl_down_sync(0xffffffffu, ss, o);
        }
        if (lane == 0) {
            float mu  = s * (1.f / 512.f);
            float var = ss * (1.f / 512.f) - mu * mu;
            g_stats[(bd * NG + g) * 2 + 0] = mu;
            g_stats[(bd * NG + g) * 2 + 1] = rsqrtf(var + 1e-5f);
        }
    }
}

__global__ void gn_norm_transpose(const float* __restrict__ x,
                                  const float* __restrict__ w,
                                  const float* __restrict__ bia) {
    int bd = blockIdx.x, ct = blockIdx.y;
    __shared__ float s[32][33];
    int tx = threadIdx.x, ty = threadIdx.y;
    const float* xb = x + (size_t)bd * Cc * Tt;
    #pragma unroll
    for (int k = 0; k < 4; k++) {
        int cl = ty + 8 * k;
        s[cl][tx] = xb[(ct * 32 + cl) * Tt + tx];
    }
    __syncthreads();
    float* ob = g_xt + (size_t)bd * Tt * Cc;
    int c = ct * 32 + tx;
    int g = c >> 4;
    float mu = g_stats[(bd * NG + g) * 2 + 0];
    float rs = g_stats[(bd * NG + g) * 2 + 1];
    float ww = w[c] * rs;
    float bb = bia[c] - mu * ww;
    #pragma unroll
    for (int k = 0; k < 4; k++) {
        int t = ty + 8 * k;
        ob[t * Cc + c] = s[tx][t] * ww + bb;
    }
}

// ---------------- time-emb GEMM (M=64, FFMA) ----------------
__global__ void __launch_bounds__(256) time_gemm(
    const float* __restrict__ temb,
    const float* __restrict__ w0, const float* __restrict__ w1, const float* __restrict__ w2,
    const float* __restrict__ b0, const float* __restrict__ b1, const float* __restrict__ b2)
{
    int nb = blockIdx.x, mb = blockIdx.y, p = blockIdx.z;
    const float* W  = (p == 0) ? w0 : (p == 1) ? w1 : w2;
    const float* Bi = (p == 0) ? b0 : (p == 1) ? b1 : b2;
    __shared__ float st[8][TDIMv];
    int tid = threadIdx.x;
    const float4* tp = (const float4*)(temb + (size_t)mb * 8 * TDIMv);
    float4* sp = (float4*)&st[0][0];
    #pragma unroll
    for (int i = 0; i < 8; i++) sp[tid + 256 * i] = tp[tid + 256 * i];
    __syncthreads();
    int n  = nb * 64 + (tid & 63);
    int m0 = (tid >> 6) * 2;
    const float4* wp = (const float4*)(W + (size_t)n * TDIMv);
    const float4* t0 = (const float4*)&st[m0][0];
    const float4* t1 = (const float4*)&st[m0 + 1][0];
    float a0 = 0.f, a1 = 0.f;
    #pragma unroll 4
    for (int k = 0; k < TDIMv / 4; k++) {
        float4 w4 = wp[k];
        float4 x0 = t0[k], x1 = t1[k];
        a0 += w4.x * x0.x + w4.y * x0.y + w4.z * x0.z + w4.w * x0.w;
        a1 += w4.x * x1.x + w4.y * x1.y + w4.z * x1.z + w4.w * x1.w;
    }
    float bias = Bi[n];
    int m = mb * 8 + m0;
    g_time[((size_t)p * (Bb * Tt) + m) * Cc + n]     = a0 + bias;
    g_time[((size_t)p * (Bb * Tt) + m + 1) * Cc + n] = a1 + bias;
}

// ---------------- shared GEMM helpers ----------------
__device__ __forceinline__ void mma_tf32(float* c, const uint32_t* a, const uint32_t* b) {
    asm volatile("mma.sync.aligned.m16n8k8.row.col.f32.tf32.tf32.f32 "
        "{%0,%1,%2,%3}, {%4,%5,%6,%7}, {%8,%9}, {%0,%1,%2,%3};"
        : "+f"(c[0]), "+f"(c[1]), "+f"(c[2]), "+f"(c[3])
        : "r"(a[0]), "r"(a[1]), "r"(a[2]), "r"(a[3]), "r"(b[0]), "r"(b[1]));
}
__device__ __forceinline__ void cpa16(uint32_t s, const void* g) {
    asm volatile("cp.async.cg.shared.global [%0], [%1], 16;" :: "r"(s), "l"(g));
}
__device__ __forceinline__ void cpcommit() { asm volatile("cp.async.commit_group;"); }
template<int Np> __device__ __forceinline__ void cpwait() {
    asm volatile("cp.async.wait_group %0;" :: "n"(Np));
}

#define ASTR 20                       // padded row stride (floats): LDS conflict-free

// ================= gemm256: BM=256, BN=128, BK=16, 4-stage, warp 64x64 =================
// (R6 kernel — best measured per-GEMM: ~120 TF/s on QKV)
#define SA_STAGE (256 * ASTR)
#define SB_STAGE (128 * ASTR)
#define G256_STAGES 4
#define G256_SMEM (G256_STAGES * (SA_STAGE + SB_STAGE) * 4)

__global__ void __launch_bounds__(256) gemm256(
    const float* __restrict__ A, size_t Asz,
    const float* __restrict__ w0, const float* __restrict__ w1, const float* __restrict__ w2,
    const float* __restrict__ bb0, const float* __restrict__ bb1, const float* __restrict__ bb2,
    const float* __restrict__ resid,
    float* __restrict__ Cout, size_t Csz, int M, int N, int K)
{
    extern __shared__ float smem[];
    float* sA = smem;
    float* sB = smem + G256_STAGES * SA_STAGE;
    int z = blockIdx.z;
    const float* W    = (z == 0) ? w0  : (z == 1) ? w1  : w2;
    const float* bias = (z == 0) ? bb0 : (z == 1) ? bb1 : bb2;
    A += (size_t)z * Asz;
    float* Cz = Cout + (size_t)z * Csz;

    int tid = threadIdx.x;
    int m0 = blockIdx.y * 256, n0 = blockIdx.x * 128;
    int row = tid >> 1;
    int kq  = (tid & 1) * 8;
    const float* Ag0 = A + (size_t)(m0 + row) * K + kq;
    const float* Ag1 = Ag0 + (size_t)128 * K;
    const float* Wg  = W + (size_t)(n0 + row) * K + kq;
    uint32_t sa0 = (uint32_t)__cvta_generic_to_shared(sA) + (row * ASTR + kq) * 4;
    uint32_t sa1 = sa0 + 128 * ASTR * 4;
    uint32_t sb0 = (uint32_t)__cvta_generic_to_shared(sB) + (row * ASTR + kq) * 4;

    float acc[4][8][4];
    #pragma unroll
    for (int i = 0; i < 4; i++)
        #pragma unroll
        for (int j = 0; j < 8; j++)
            #pragma unroll
            for (int q = 0; q < 4; q++) acc[i][j][q] = 0.f;

    int lane = tid & 31, warp = tid >> 5;
    int wm = (warp >> 1) * 64, wn = (warp & 1) * 64;
    int gid = lane >> 2, tig = lane & 3;
    int NIT = K >> 4;

    #define G256_ISSUE(t) { uint32_t oA = ((t) & 3) * (SA_STAGE * 4);              \
        uint32_t oB = ((t) & 3) * (SB_STAGE * 4);                                  \
        const float* ga0 = Ag0 + (t) * 16; const float* ga1 = Ag1 + (t) * 16;      \
        const float* gb  = Wg  + (t) * 16;                                         \
        cpa16(sa0 + oA, ga0); cpa16(sa0 + oA + 16, ga0 + 4);                       \
        cpa16(sa1 + oA, ga1); cpa16(sa1 + oA + 16, ga1 + 4);                       \
        cpa16(sb0 + oB, gb);  cpa16(sb0 + oB + 16, gb + 4); }

    G256_ISSUE(0); cpcommit();
    if (NIT > 1) { G256_ISSUE(1); } cpcommit();
    if (NIT > 2) { G256_ISSUE(2); } cpcommit();

    for (int i = 0; i < NIT; i++) {
        cpwait<2>();
        __syncthreads();
        const uint32_t* Ab = (const uint32_t*)(sA + (i & 3) * SA_STAGE);
        const uint32_t* Bw = (const uint32_t*)(sB + (i & 3) * SB_STAGE);
        #pragma unroll
        for (int kk = 0; kk < 16; kk += 8) {
            uint32_t af[4][4], bf[8][2];
            #pragma unroll
            for (int mt = 0; mt < 4; mt++) {
                int r0 = wm + mt * 16 + gid;
                af[mt][0] = Ab[(r0    ) * ASTR + kk + tig];
                af[mt][1] = Ab[(r0 + 8) * ASTR + kk + tig];
                af[mt][2] = Ab[(r0    ) * ASTR + kk + tig + 4];
                af[mt][3] = Ab[(r0 + 8) * ASTR + kk + tig + 4];
            }
            #pragma unroll
            for (int nt = 0; nt < 8; nt++) {
                int c0 = wn + nt * 8 + gid;
                bf[nt][0] = Bw[c0 * ASTR + kk + tig];
                bf[nt][1] = Bw[c0 * ASTR + kk + tig + 4];
            }
            #pragma unroll
            for (int mt = 0; mt < 4; mt++)
                #pragma unroll
                for (int nt = 0; nt < 8; nt++)
                    mma_tf32(acc[mt][nt], af[mt], bf[nt]);
        }
        if (i + 3 < NIT) { G256_ISSUE(i + 3); }
        cpcommit();
    }

    #pragma unroll
    for (int mt = 0; mt < 4; mt++) {
        int r0 = m0 + wm + mt * 16 + gid;
        #pragma unroll
        for (int nt = 0; nt < 8; nt++) {
            int col = n0 + wn + nt * 8 + tig * 2;
            float b0v = bias[col], b1v = bias[col + 1];
            float* c = acc[mt][nt];
            float2 o0 = make_float2(c[0] + b0v, c[1] + b1v);
            float2 o1 = make_float2(c[2] + b0v, c[3] + b1v);
            if (resid) {
                float2 r0v = *(const float2*)(resid + (size_t)r0 * N + col);
                float2 r1v = *(const float2*)(resid + (size_t)(r0 + 8) * N + col);
                o0.x += r0v.x; o0.y += r0v.y; o1.x += r1v.x; o1.y += r1v.y;
            }
            *(float2*)(Cz + (size_t)r0 * N + col) = o0;
            *(float2*)(Cz + (size_t)(r0 + 8) * N + col) = o1;
        }
    }
}

// ================= gemm128: BM=BN=128, BK=16, 4-stage, warp 64x32 =================
// (R5 kernel — better for small M: more blocks in flight)
#define SSTR (128 * ASTR)
#define G128_STAGES 4
#define G128_SMEM (G128_STAGES * SSTR * 2 * 4)

__global__ void __launch_bounds__(256) gemm128(
    const float* __restrict__ A, size_t Asz,
    const float* __restrict__ w0, const float* __restrict__ w1, const float* __restrict__ w2,
    const float* __restrict__ bb0, const float* __restrict__ bb1, const float* __restrict__ bb2,
    const float* __restrict__ resid,
    float* __restrict__ Cout, size_t Csz, int M, int N, int K)
{
    extern __shared__ float smem[];
    float* sA = smem;
    float* sB = smem + G128_STAGES * SSTR;
    int z = blockIdx.z;
    const float* W    = (z == 0) ? w0  : (z == 1) ? w1  : w2;
    const float* bias = (z == 0) ? bb0 : (z == 1) ? bb1 : bb2;
    A += (size_t)z * Asz;
    float* Cz = Cout + (size_t)z * Csz;

    int tid = threadIdx.x;
    int m0 = blockIdx.y * 128, n0 = blockIdx.x * 128;
    int row = tid >> 1;
    int kq  = (tid & 1) * 8;
    const float* Ag = A + (size_t)(m0 + row) * K + kq;
    const float* Wg = W + (size_t)(n0 + row) * K + kq;
    uint32_t sAa = (uint32_t)__cvta_generic_to_shared(sA) + (row * ASTR + kq) * 4;
    uint32_t sBa = (uint32_t)__cvta_generic_to_shared(sB) + (row * ASTR + kq) * 4;

    float acc[4][4][4];
    #pragma unroll
    for (int i = 0; i < 4; i++)
        #pragma unroll
        for (int j = 0; j < 4; j++)
            #pragma unroll
            for (int q = 0; q < 4; q++) acc[i][j][q] = 0.f;

    int lane = tid & 31, warp = tid >> 5;
    int wm = (warp >> 2) * 64, wn = (warp & 3) * 32;
    int gid = lane >> 2, tig = lane & 3;
    int NIT = K >> 4;

    #define G128_ISSUE(t) { uint32_t bo = ((t) & 3) * (SSTR * 4);                  \
        const float* ga = Ag + (t) * 16; const float* gb = Wg + (t) * 16;          \
        cpa16(sAa + bo, ga); cpa16(sAa + bo + 16, ga + 4);                         \
        cpa16(sBa + bo, gb); cpa16(sBa + bo + 16, gb + 4); }

    G128_ISSUE(0); cpcommit();
    if (NIT > 1) { G128_ISSUE(1); } cpcommit();
    if (NIT > 2) { G128_ISSUE(2); } cpcommit();

    for (int i = 0; i < NIT; i++) {
        cpwait<2>();
        __syncthreads();
        const uint32_t* Ab = (const uint32_t*)(sA + (i & 3) * SSTR);
        const uint32_t* Bw = (const uint32_t*)(sB + (i & 3) * SSTR);
        #pragma unroll
        for (int kk = 0; kk < 16; kk += 8) {
            uint32_t af[4][4], bf[4][2];
            #pragma unroll
            for (int mt = 0; mt < 4; mt++) {
                int r0 = wm + mt * 16 + gid;
                af[mt][0] = Ab[(r0    ) * ASTR + kk + tig];
                af[mt][1] = Ab[(r0 + 8) * ASTR + kk + tig];
                af[mt][2] = Ab[(r0    ) * ASTR + kk + tig + 4];
                af[mt][3] = Ab[(r0 + 8) * ASTR + kk + tig + 4];
            }
            #pragma unroll
            for (int nt = 0; nt < 4; nt++) {
                int c0 = wn + nt * 8 + gid;
                bf[nt][0] = Bw[c0 * ASTR + kk + tig];
                bf[nt][1] = Bw[c0 * ASTR + kk + tig + 4];
            }
            #pragma unroll
            for (int mt = 0; mt < 4; mt++)
                #pragma unroll
                for (int nt = 0; nt < 4; nt++)
                    mma_tf32(acc[mt][nt], af[mt], bf[nt]);
        }
        if (i + 3 < NIT) { G128_ISSUE(i + 3); }
        cpcommit();
    }

    #pragma unroll
    for (int mt = 0; mt < 4; mt++) {
        int r0 = m0 + wm + mt * 16 + gid;
        #pragma unroll
        for (int nt = 0; nt < 4; nt++) {
            int col = n0 + wn + nt * 8 + tig * 2;
            float b0v = bias[col], b1v = bias[col + 1];
            float* c = acc[mt][nt];
            float2 o0 = make_float2(c[0] + b0v, c[1] + b1v);
            float2 o1 = make_float2(c[2] + b0v, c[3] + b1v);
            if (resid) {
                float2 r0v = *(const float2*)(resid + (size_t)r0 * N + col);
                float2 r1v = *(const float2*)(resid + (size_t)(r0 + 8) * N + col);
                o0.x += r0v.x; o0.y += r0v.y; o1.x += r1v.x; o1.y += r1v.y;
            }
            *(float2*)(Cz + (size_t)r0 * N + col) = o0;
            *(float2*)(Cz + (size_t)(r0 + 8) * N + col) = o1;
        }
    }
}

// ---------------- RPE: emb = time + feats@dw^T + db; E = silu(emb) ----------------
__global__ void emb_silu(const int* __restrict__ fi,
                         const float* __restrict__ dw0, const float* __restrict__ db0,
                         const float* __restrict__ dw1, const float* __restrict__ db1,
                         const float* __restrict__ dw2, const float* __restrict__ db2) {
    int e = blockIdx.x;
    int p = blockIdx.y;
    const float* dw = (p == 0) ? dw0 : (p == 1) ? dw1 : dw2;
    const float* db = (p == 0) ? db0 : (p == 1) ? db1 : db2;
    int b = e / (Tt * Tt);
    int t = (e / Tt) % Tt;
    int s = e % Tt;
    int d = fi[b * Tt + t] - fi[b * Tt + s];
    float df = (float)d;
    float f0 = log1pf(fmaxf(df, 0.f));
    float f1 = log1pf(fmaxf(-df, 0.f));
    float f2 = (d == 0) ? 1.f : 0.f;
    int c = threadIdx.x;
    float v = g_time[((p * Bb + b) * Tt + t) * Cc + c]
            + f0 * dw[c * 3 + 0] + f1 * dw[c * 3 + 1] + f2 * dw[c * 3 + 2] + db[c];
    float sg = 1.f / (1.f + expf(-v));
    g_E[((size_t)p * Bb * Tt * Tt + e) * Cc + c] = v * sg;
}

// ---------------- fused attention: block = (b,h) x GA consecutive d; 512 threads ----------------
#define QROW 68
#define ATT_SMEM_BYTES ((3*GA*Tt*QROW + GA*Tt*33 + 32) * 4)

__global__ void __launch_bounds__(512) attn_kernel(const int* __restrict__ mask) {
    extern __shared__ float sdyn[];
    int x = blockIdx.x;
    int dg = x & 127;
    int h  = (x >> 7) & 7;
    int b  = x >> 10;
    int d0 = dg * GA;
    float* sq   = sdyn;
    float* sk   = sq + GA * Tt * QROW;
    float* sv   = sk + GA * Tt * QROW;
    float* satt = sv + GA * Tt * QROW;
    int*   sm   = (int*)(satt + GA * Tt * 33);
    int tid = threadIdx.x;
    const float scale = 0.125f;

    const float* base = g_qkv + ((size_t)(b * Dd + d0) * Tt) * (3 * Cc) + h * Fv;
    #pragma unroll
    for (int i = 0; i < 4; i++) {
        int idx = tid + 512 * i;
        int g  = idx >> 9;
        int t  = (idx >> 4) & 31;
        int f4 = idx & 15;
        const float* r = base + ((size_t)g * Tt + t) * (3 * Cc) + f4 * 4;
        float4 qv = *(const float4*)(r);
        float4 kv = *(const float4*)(r + Cc);
        float4 vv = *(const float4*)(r + 2 * Cc);
        qv.x *= scale; qv.y *= scale; qv.z *= scale; qv.w *= scale;
        *(float4*)(sq + (g * Tt + t) * QROW + f4 * 4) = qv;
        *(float4*)(sk + (g * Tt + t) * QROW + f4 * 4) = kv;
        *(float4*)(sv + (g * Tt + t) * QROW + f4 * 4) = vv;
    }
    if (tid < Tt) sm[tid] = mask[b * Tt + tid];
    __syncthreads();

    const float* Rk = g_R + ((size_t)(1 * Bb + b) * (Tt * Tt)) * Cc + h * Fv;
    const float* Rq = g_R + ((size_t)(0 * Bb + b) * (Tt * Tt)) * Cc + h * Fv;
    #pragma unroll
    for (int i = 0; i < 2; i++) {
        int e = tid + 512 * i;
        int t = e >> 5, s = e & 31;
        const float4* rk = (const float4*)(Rk + (size_t)(t * Tt + s) * Cc);
        const float4* rq = (const float4*)(Rq + (size_t)(s * Tt + t) * Cc);
        float acc[GA] = {0.f, 0.f, 0.f, 0.f};
        #pragma unroll
        for (int j = 0; j < 16; j++) {
            float4 a4 = rk[j], b4 = rq[j];
            #pragma unroll
            for (int g = 0; g < GA; g++) {
                float4 q4 = *(const float4*)(sq + (g * Tt + t) * QROW + j * 4);
                float4 k4 = *(const float4*)(sk + (g * Tt + s) * QROW + j * 4);
                acc[g] += q4.x * (k4.x + a4.x) + scale * k4.x * b4.x;
                acc[g] += q4.y * (k4.y + a4.y) + scale * k4.y * b4.y;
                acc[g] += q4.z * (k4.z + a4.z) + scale * k4.z * b4.z;
                acc[g] += q4.w * (k4.w + a4.w) + scale * k4.w * b4.w;
            }
        }
        bool ok = (sm[t] == sm[s]);
        #pragma unroll
        for (int g = 0; g < GA; g++)
            satt[(g * Tt + t) * 33 + s] = ok ? acc[g] : -1e30f;
    }
    __syncthreads();

    int warp = tid >> 5, lane = tid & 31;
    for (int r = warp * 8; r < warp * 8 + 8; r++) {
        float v = satt[r * 33 + lane];
        float m = v;
        #pragma unroll
        for (int o = 16; o; o >>= 1) m = fmaxf(m, __shfl_xor_sync(0xffffffffu, m, o));
        float ev = expf(v - m);
        float ssum = ev;
        #pragma unroll
        for (int o = 16; o; o >>= 1) ssum += __shfl_xor_sync(0xffffffffu, ssum, o);
        satt[r * 33 + lane] = ev / ssum;
    }
    __syncthreads();

    const float* Rv = g_R + ((size_t)(2 * Bb + b) * (Tt * Tt)) * Cc + h * Fv;
    float* ob = g_attout + ((size_t)(b * Dd + d0) * Tt) * Cc + h * Fv;
    #pragma unroll
    for (int i = 0; i < 4; i++) {
        int e = tid + 512 * i;
        int t = e >> 6, f = e & 63;
        const float* rv = Rv + (size_t)(t * Tt) * Cc + f;
        float acc[GA] = {0.f, 0.f, 0.f, 0.f};
        #pragma unroll
        for (int s = 0; s < Tt; s++) {
            float rvv = rv[(size_t)s * Cc];
            #pragma unroll
            for (int g = 0; g < GA; g++)
                acc[g] += satt[(g * Tt + t) * 33 + s] * (sv[(g * Tt + s) * QROW + f] + rvv);
        }
        #pragma unroll
        for (int g = 0; g < GA; g++)
            ob[((size_t)g * Tt + t) * Cc + f] = acc[g];
    }
}

// ---------------- final transpose [B,D,T,C] -> [B,D,C,T] ----------------
__global__ void transpose_out(float* __restrict__ out) {
    int bd = blockIdx.x, ct = blockIdx.y;
    __shared__ float s[32][33];
    int tx = threadIdx.x, ty = threadIdx.y;
    const float* yb = g_y + (size_t)bd * Tt * Cc;
    #pragma unroll
    for (int k = 0; k < 4; k++) {
        int t = ty + 8 * k;
        s[t][tx] = yb[t * Cc + ct * 32 + tx];
    }
    __syncthreads();
    float* ob = out + (size_t)bd * Cc * Tt;
    #pragma unroll
    for (int k = 0; k < 4; k++) {
        int c = ct * 32 + ty + 8 * k;
        ob[c * Tt + tx] = s[tx][ty + 8 * k];
    }
}

// ---------------- launch ----------------
extern "C" void kernel_launch(void* const* d_in, const int* in_sizes, int n_in,
                              void* d_out, int out_size) {
    const float* x      = (const float*)d_in[0];
    const float* temb   = (const float*)d_in[1];
    const int*   fi     = (const int*)d_in[2];
    const int*   amask  = (const int*)d_in[3];
    const float* norm_w = (const float*)d_in[4];
    const float* norm_b = (const float*)d_in[5];
    const float* qkv_w  = (const float*)d_in[6];
    const float* qkv_b  = (const float*)d_in[7];
    const float* proj_w = (const float*)d_in[8];
    const float* proj_b = (const float*)d_in[9];
    float* out = (float*)d_out;

    float *p_xt, *p_time, *p_E, *p_R, *p_qkv, *p_attout, *p_y;
    cudaGetSymbolAddress((void**)&p_xt, g_xt);
    cudaGetSymbolAddress((void**)&p_time, g_time);
    cudaGetSymbolAddress((void**)&p_E, g_E);
    cudaGetSymbolAddress((void**)&p_R, g_R);
    cudaGetSymbolAddress((void**)&p_qkv, g_qkv);
    cudaGetSymbolAddress((void**)&p_attout, g_attout);
    cudaGetSymbolAddress((void**)&p_y, g_y);

    cudaFuncSetAttribute(attn_kernel, cudaFuncAttributeMaxDynamicSharedMemorySize,
                         ATT_SMEM_BYTES);
    cudaFuncSetAttribute(gemm256, cudaFuncAttributeMaxDynamicSharedMemorySize,
                         G256_SMEM);
    cudaFuncSetAttribute(gemm128, cudaFuncAttributeMaxDynamicSharedMemorySize,
                         G128_SMEM);

    dim3 tb(32, 8);

    // 1. group norm
    gn_stats<<<Bb * Dd, 256>>>(x);
    gn_norm_transpose<<<dim3(Bb * Dd, Cc / 32), tb>>>(x, norm_w, norm_b);

    // 2. time GEMMs (all 3 p, one launch)
    time_gemm<<<dim3(8, 8, 3), 256>>>(temb,
        (const float*)d_in[12], (const float*)d_in[18], (const float*)d_in[24],
        (const float*)d_in[13], (const float*)d_in[19], (const float*)d_in[25]);

    // 3. QKV GEMM: [32768, 512] @ [512, 1536]^T  (4th launch -> ncu target)
    gemm256<<<dim3((3 * Cc) / 128, (Bb * Dd * Tt) / 256, 1), 256, G256_SMEM>>>(
        p_xt, 0, qkv_w, qkv_w, qkv_w, qkv_b, qkv_b, qkv_b,
        nullptr, p_qkv, 0, Bb * Dd * Tt, 3 * Cc, Cc);

    // 4. emb + silu (all 3 p)
    emb_silu<<<dim3(Bb * Tt * Tt, 3), Cc>>>(
        fi,
        (const float*)d_in[10], (const float*)d_in[11],
        (const float*)d_in[16], (const float*)d_in[17],
        (const float*)d_in[22], (const float*)d_in[23]);

    // 5. RPE out GEMMs, batched z=3: [2048, 512] @ [512, 512]^T (small M -> 128 tile)
    gemm128<<<dim3(Cc / 128, (Bb * Tt * Tt) / 128, 3), 256, G128_SMEM>>>(
        p_E, (size_t)Bb * Tt * Tt * Cc,
        (const float*)d_in[14], (const float*)d_in[20], (const float*)d_in[26],
        (const float*)d_in[15], (const float*)d_in[21], (const float*)d_in[27],
        nullptr, p_R, (size_t)Bb * Tt * Tt * Cc,
        Bb * Tt * Tt, Cc, Cc);

    // 6. attention
    attn_kernel<<<Bb * Hh * (Dd / GA), 512, ATT_SMEM_BYTES>>>(amask);

    // 7. proj GEMM + residual (large M -> 256 tile)
    gemm256<<<dim3(Cc / 128, (Bb * Dd * Tt) / 256, 1), 256, G256_SMEM>>>(
        p_attout, 0, proj_w, proj_w, proj_w, proj_b, proj_b, proj_b,
        p_xt, p_y, 0, Bb * Dd * Tt, Cc, Cc);

    // 8. output transpose
    transpose_out<<<dim3(Bb * Dd, Cc / 32), tb>>>(out);
}

// round 15
// speedup vs baseline: 1.8308x; 1.8308x over previous
#include <cuda_runtime.h>
#include <cuda_bf16.h>
#include <math.h>
#include <stdint.h>

#define Bb 2
#define Dd 512
#define Cc 512
#define Tt 32
#define TDIMv 1024
#define Hh 8
#define Fv 64
#define NG 32
#define GA 4

// ---------------- scratch (device globals; no allocation allowed) ----------------
__device__ float g_stats[Bb*Dd*NG*2];
__device__ float g_xt[(size_t)Bb*Dd*Tt*Cc];                  // normalized x fp32 (residual)
__device__ __nv_bfloat16 g_xt_bf[(size_t)Bb*Dd*Tt*Cc];       // bf16 copy (QKV GEMM input)
__device__ float g_time[3*Bb*Tt*Cc];                         // [p,b,t,C]
__device__ __nv_bfloat16 g_E_bf[(size_t)3*Bb*Tt*Tt*Cc];      // silu(emb) bf16 (R GEMM input)
__device__ float g_R[(size_t)3*Bb*Tt*Tt*Cc];                 // rpe bias fp32
__device__ float g_qkv[(size_t)Bb*Dd*Tt*3*Cc];               // [B,D,T,3C] fp32
__device__ __nv_bfloat16 g_attout_bf[(size_t)Bb*Dd*Tt*Cc];   // attn out bf16 (proj input)
__device__ float g_y[(size_t)Bb*Dd*Tt*Cc];                   // [B,D,T,C]
// bf16 weights: qkv(786432) | proj(262144) | qout | kout | vout (262144 each)
__device__ __nv_bfloat16 g_wbf[786432 + 4*262144];

// ---------------- group-norm ----------------
__global__ void gn_stats(const float* __restrict__ x) {
    int bd = blockIdx.x;
    const float4* xp = (const float4*)(x + (size_t)bd * Cc * Tt);
    int warp = threadIdx.x >> 5, lane = threadIdx.x & 31;
    for (int gi = 0; gi < 4; gi++) {
        int g = warp + gi * 8;
        float s = 0.f, ss = 0.f;
        #pragma unroll
        for (int j = 0; j < 4; j++) {
            float4 v = xp[g * 128 + lane + 32 * j];
            s  += v.x + v.y + v.z + v.w;
            ss += v.x * v.x + v.y * v.y + v.z * v.z + v.w * v.w;
        }
        #pragma unroll
        for (int o = 16; o; o >>= 1) {
            s  += __shfl_down_sync(0xffffffffu, s, o);
            ss += __shfl_down_sync(0xffffffffu, ss, o);
        }
        if (lane == 0) {
            float mu  = s * (1.f / 512.f);
            float var = ss * (1.f / 512.f) - mu * mu;
            g_stats[(bd * NG + g) * 2 + 0] = mu;
            g_stats[(bd * NG + g) * 2 + 1] = rsqrtf(var + 1e-5f);
        }
    }
}

__global__ void gn_norm_transpose(const float* __restrict__ x,
                                  const float* __restrict__ w,
                                  const float* __restrict__ bia) {
    int bd = blockIdx.x, ct = blockIdx.y;
    __shared__ float s[32][33];
    int tx = threadIdx.x, ty = threadIdx.y;
    const float* xb = x + (size_t)bd * Cc * Tt;
    #pragma unroll
    for (int k = 0; k < 4; k++) {
        int cl = ty + 8 * k;
        s[cl][tx] = xb[(ct * 32 + cl) * Tt + tx];
    }
    __syncthreads();
    float* ob = g_xt + (size_t)bd * Tt * Cc;
    __nv_bfloat16* obf = g_xt_bf + (size_t)bd * Tt * Cc;
    int c = ct * 32 + tx;
    int g = c >> 4;
    float mu = g_stats[(bd * NG + g) * 2 + 0];
    float rs = g_stats[(bd * NG + g) * 2 + 1];
    float ww = w[c] * rs;
    float bb = bia[c] - mu * ww;
    #pragma unroll
    for (int k = 0; k < 4; k++) {
        int t = ty + 8 * k;
        float v = s[tx][t] * ww + bb;
        ob[t * Cc + c] = v;
        obf[t * Cc + c] = __float2bfloat16(v);
    }
}

// ---------------- weight conversion fp32 -> bf16 ----------------
__global__ void cvt_w(const float* __restrict__ s0, const float* __restrict__ s1,
                      const float* __restrict__ s2, const float* __restrict__ s3,
                      const float* __restrict__ s4) {
    int seg = blockIdx.y;
    const float* src; int size; int off;
    if      (seg == 0) { src = s0; size = 786432; off = 0; }
    else if (seg == 1) { src = s1; size = 262144; off = 786432; }
    else if (seg == 2) { src = s2; size = 262144; off = 1048576; }
    else if (seg == 3) { src = s3; size = 262144; off = 1310720; }
    else               { src = s4; size = 262144; off = 1572864; }
    int i4 = (blockIdx.x * 256 + threadIdx.x) * 4;
    if (i4 >= size) return;
    float4 v = *(const float4*)(src + i4);
    __nv_bfloat16* d = g_wbf + off + i4;
    d[0] = __float2bfloat16(v.x);
    d[1] = __float2bfloat16(v.y);
    d[2] = __float2bfloat16(v.z);
    d[3] = __float2bfloat16(v.w);
}

// ---------------- time-emb GEMM (M=64, FFMA, fp32) ----------------
__global__ void __launch_bounds__(256) time_gemm(
    const float* __restrict__ temb,
    const float* __restrict__ w0, const float* __restrict__ w1, const float* __restrict__ w2,
    const float* __restrict__ b0, const float* __restrict__ b1, const float* __restrict__ b2)
{
    int nb = blockIdx.x, mb = blockIdx.y, p = blockIdx.z;
    const float* W  = (p == 0) ? w0 : (p == 1) ? w1 : w2;
    const float* Bi = (p == 0) ? b0 : (p == 1) ? b1 : b2;
    __shared__ float st[8][TDIMv];
    int tid = threadIdx.x;
    const float4* tp = (const float4*)(temb + (size_t)mb * 8 * TDIMv);
    float4* sp = (float4*)&st[0][0];
    #pragma unroll
    for (int i = 0; i < 8; i++) sp[tid + 256 * i] = tp[tid + 256 * i];
    __syncthreads();
    int n  = nb * 64 + (tid & 63);
    int m0 = (tid >> 6) * 2;
    const float4* wp = (const float4*)(W + (size_t)n * TDIMv);
    const float4* t0 = (const float4*)&st[m0][0];
    const float4* t1 = (const float4*)&st[m0 + 1][0];
    float a0 = 0.f, a1 = 0.f;
    #pragma unroll 4
    for (int k = 0; k < TDIMv / 4; k++) {
        float4 w4 = wp[k];
        float4 x0 = t0[k], x1 = t1[k];
        a0 += w4.x * x0.x + w4.y * x0.y + w4.z * x0.z + w4.w * x0.w;
        a1 += w4.x * x1.x + w4.y * x1.y + w4.z * x1.z + w4.w * x1.w;
    }
    float bias = Bi[n];
    int m = mb * 8 + m0;
    g_time[((size_t)p * (Bb * Tt) + m) * Cc + n]     = a0 + bias;
    g_time[((size_t)p * (Bb * Tt) + m + 1) * Cc + n] = a1 + bias;
}

// ---------------- bf16 tensor-core GEMM ----------------
// C = A @ W^T + bias (+resid), fp32 accumulate/output. A:[M][K] bf16, W:[N][K] bf16.
// BM=BN=128, BK=32, 3-stage cp.async, 256 thr (8 warps 2m x 4n), warp 64x32.
// M,N multiples of 128; K multiple of 32. z: A += z*Asz, W += z*Wsz, bias by z.
__device__ __forceinline__ void mma_bf16(float* c, const uint32_t* a, const uint32_t* b) {
    asm volatile("mma.sync.aligned.m16n8k16.row.col.f32.bf16.bf16.f32 "
        "{%0,%1,%2,%3}, {%4,%5,%6,%7}, {%8,%9}, {%0,%1,%2,%3};"
        : "+f"(c[0]), "+f"(c[1]), "+f"(c[2]), "+f"(c[3])
        : "r"(a[0]), "r"(a[1]), "r"(a[2]), "r"(a[3]), "r"(b[0]), "r"(b[1]));
}
__device__ __forceinline__ void cpa16(uint32_t s, const void* g) {
    asm volatile("cp.async.cg.shared.global [%0], [%1], 16;" :: "r"(s), "l"(g));
}
__device__ __forceinline__ void cpcommit() { asm volatile("cp.async.commit_group;"); }
template<int Np> __device__ __forceinline__ void cpwait() {
    asm volatile("cp.async.wait_group %0;" :: "n"(Np));
}

#define RSW 20                       // smem row stride in words (40 bf16, 80B): conflict-free
#define STGW (128 * RSW)             // words per stage per matrix (2560)
#define GBF_SMEM (3 * STGW * 2 * 4)  // 61440 bytes

__global__ void __launch_bounds__(256, 2) gemm_bf(
    const __nv_bfloat16* __restrict__ A, size_t Asz,
    const __nv_bfloat16* __restrict__ Wb, size_t Wsz,
    const float* __restrict__ bb0, const float* __restrict__ bb1, const float* __restrict__ bb2,
    const float* __restrict__ resid,
    float* __restrict__ Cout, size_t Csz, int M, int N, int K)
{
    extern __shared__ uint32_t smw[];
    int z = blockIdx.z;
    const float* bias = (z == 0) ? bb0 : (z == 1) ? bb1 : bb2;
    A  += (size_t)z * Asz;
    const __nv_bfloat16* W = Wb + (size_t)z * Wsz;
    float* Cz = Cout + (size_t)z * Csz;

    int tid = threadIdx.x;
    int m0 = blockIdx.y * 128, n0 = blockIdx.x * 128;
    uint32_t sbyte = (uint32_t)__cvta_generic_to_shared(smw);

    float acc[4][4][4];
    #pragma unroll
    for (int i = 0; i < 4; i++)
        #pragma unroll
        for (int j = 0; j < 4; j++)
            #pragma unroll
            for (int q = 0; q < 4; q++) acc[i][j][q] = 0.f;

    int lane = tid & 31, warp = tid >> 5;
    int wm = (warp >> 2) * 64, wn = (warp & 3) * 32;
    int gid = lane >> 2, tig = lane & 3;
    int NCH = K >> 5;

    const __nv_bfloat16* Ag = A + (size_t)m0 * K;
    const __nv_bfloat16* Wg = W + (size_t)n0 * K;

    #define GBF_ISSUE(t) { int st = (t) % 3;                                       \
        uint32_t oA = sbyte + st * (STGW * 4);                                     \
        uint32_t oB = oA + 3 * STGW * 4;                                           \
        _Pragma("unroll")                                                          \
        for (int ii = 0; ii < 2; ii++) {                                           \
            int idx = tid + 256 * ii; int r = idx >> 2; int cu = idx & 3;          \
            cpa16(oA + r * 80 + cu * 16, Ag + (size_t)r * K + (t) * 32 + cu * 8);  \
            cpa16(oB + r * 80 + cu * 16, Wg + (size_t)r * K + (t) * 32 + cu * 8);  \
        }                                                                          \
        cpcommit(); }

    GBF_ISSUE(0);
    if (NCH > 1) { GBF_ISSUE(1); }

    for (int c = 0; c < NCH; c++) {
        cpwait<1>();
        __syncthreads();
        if (c + 2 < NCH) { GBF_ISSUE(c + 2); }
        int st = c % 3;
        const uint32_t* S  = smw + st * STGW;
        const uint32_t* SB = smw + 3 * STGW + st * STGW;
        #pragma unroll
        for (int kk = 0; kk < 2; kk++) {
            uint32_t af[4][4], bf4[4][2];
            int ko = kk * 8;
            #pragma unroll
            for (int mt = 0; mt < 4; mt++) {
                int base = (wm + mt * 16 + gid) * RSW + ko + tig;
                af[mt][0] = S[base];
                af[mt][1] = S[base + 8 * RSW];
                af[mt][2] = S[base + 4];
                af[mt][3] = S[base + 8 * RSW + 4];
            }
            #pragma unroll
            for (int nt = 0; nt < 4; nt++) {
                int base = (wn + nt * 8 + gid) * RSW + ko + tig;
                bf4[nt][0] = SB[base];
                bf4[nt][1] = SB[base + 4];
            }
            #pragma unroll
            for (int mt = 0; mt < 4; mt++)
                #pragma unroll
                for (int nt = 0; nt < 4; nt++)
                    mma_bf16(acc[mt][nt], af[mt], bf4[nt]);
        }
        __syncthreads();
    }

    // epilogue (M,N multiples of 128 -> no guards)
    #pragma unroll
    for (int mt = 0; mt < 4; mt++) {
        int r0 = m0 + wm + mt * 16 + gid;
        #pragma unroll
        for (int nt = 0; nt < 4; nt++) {
            int col = n0 + wn + nt * 8 + tig * 2;
            float b0v = bias[col], b1v = bias[col + 1];
            float* c = acc[mt][nt];
            float2 o0 = make_float2(c[0] + b0v, c[1] + b1v);
            float2 o1 = make_float2(c[2] + b0v, c[3] + b1v);
            if (resid) {
                float2 r0v = *(const float2*)(resid + (size_t)r0 * N + col);
                float2 r1v = *(const float2*)(resid + (size_t)(r0 + 8) * N + col);
                o0.x += r0v.x; o0.y += r0v.y; o1.x += r1v.x; o1.y += r1v.y;
            }
            *(float2*)(Cz + (size_t)r0 * N + col) = o0;
            *(float2*)(Cz + (size_t)(r0 + 8) * N + col) = o1;
        }
    }
}

// ---------------- RPE: emb = time + feats@dw^T + db; E = silu(emb) -> bf16 ----------------
__global__ void emb_silu(const int* __restrict__ fi,
                         const float* __restrict__ dw0, const float* __restrict__ db0,
                         const float* __restrict__ dw1, const float* __restrict__ db1,
                         const float* __restrict__ dw2, const float* __restrict__ db2) {
    int e = blockIdx.x;
    int p = blockIdx.y;
    const float* dw = (p == 0) ? dw0 : (p == 1) ? dw1 : dw2;
    const float* db = (p == 0) ? db0 : (p == 1) ? db1 : db2;
    int b = e / (Tt * Tt);
    int t = (e / Tt) % Tt;
    int s = e % Tt;
    int d = fi[b * Tt + t] - fi[b * Tt + s];
    float df = (float)d;
    float f0 = log1pf(fmaxf(df, 0.f));
    float f1 = log1pf(fmaxf(-df, 0.f));
    float f2 = (d == 0) ? 1.f : 0.f;
    int c = threadIdx.x;
    float v = g_time[((p * Bb + b) * Tt + t) * Cc + c]
            + f0 * dw[c * 3 + 0] + f1 * dw[c * 3 + 1] + f2 * dw[c * 3 + 2] + db[c];
    float sg = 1.f / (1.f + expf(-v));
    g_E_bf[((size_t)p * Bb * Tt * Tt + e) * Cc + c] = __float2bfloat16(v * sg);
}

// ---------------- fused attention: block = (b,h) x GA consecutive d; 512 threads ----------------
#define QROW 68
#define ATT_SMEM_BYTES ((3*GA*Tt*QROW + GA*Tt*33 + 32) * 4)

__global__ void __launch_bounds__(512) attn_kernel(const int* __restrict__ mask) {
    extern __shared__ float sdyn[];
    int x = blockIdx.x;
    int dg = x & 127;
    int h  = (x >> 7) & 7;
    int b  = x >> 10;
    int d0 = dg * GA;
    float* sq   = sdyn;
    float* sk   = sq + GA * Tt * QROW;
    float* sv   = sk + GA * Tt * QROW;
    float* satt = sv + GA * Tt * QROW;
    int*   sm   = (int*)(satt + GA * Tt * 33);
    int tid = threadIdx.x;
    const float scale = 0.125f;

    const float* base = g_qkv + ((size_t)(b * Dd + d0) * Tt) * (3 * Cc) + h * Fv;
    #pragma unroll
    for (int i = 0; i < 4; i++) {
        int idx = tid + 512 * i;
        int g  = idx >> 9;
        int t  = (idx >> 4) & 31;
        int f4 = idx & 15;
        const float* r = base + ((size_t)g * Tt + t) * (3 * Cc) + f4 * 4;
        float4 qv = *(const float4*)(r);
        float4 kv = *(const float4*)(r + Cc);
        float4 vv = *(const float4*)(r + 2 * Cc);
        qv.x *= scale; qv.y *= scale; qv.z *= scale; qv.w *= scale;
        *(float4*)(sq + (g * Tt + t) * QROW + f4 * 4) = qv;
        *(float4*)(sk + (g * Tt + t) * QROW + f4 * 4) = kv;
        *(float4*)(sv + (g * Tt + t) * QROW + f4 * 4) = vv;
    }
    if (tid < Tt) sm[tid] = mask[b * Tt + tid];
    __syncthreads();

    const float* Rk = g_R + ((size_t)(1 * Bb + b) * (Tt * Tt)) * Cc + h * Fv;
    const float* Rq = g_R + ((size_t)(0 * Bb + b) * (Tt * Tt)) * Cc + h * Fv;
    #pragma unroll
    for (int i = 0; i < 2; i++) {
        int e = tid + 512 * i;
        int t = e >> 5, s = e & 31;
        const float4* rk = (const float4*)(Rk + (size_t)(t * Tt + s) * Cc);
        const float4* rq = (const float4*)(Rq + (size_t)(s * Tt + t) * Cc);
        float acc[GA] = {0.f, 0.f, 0.f, 0.f};
        #pragma unroll
        for (int j = 0; j < 16; j++) {
            float4 a4 = rk[j], b4 = rq[j];
            #pragma unroll
            for (int g = 0; g < GA; g++) {
                float4 q4 = *(const float4*)(sq + (g * Tt + t) * QROW + j * 4);
                float4 k4 = *(const float4*)(sk + (g * Tt + s) * QROW + j * 4);
                acc[g] += q4.x * (k4.x + a4.x) + scale * k4.x * b4.x;
                acc[g] += q4.y * (k4.y + a4.y) + scale * k4.y * b4.y;
                acc[g] += q4.z * (k4.z + a4.z) + scale * k4.z * b4.z;
                acc[g] += q4.w * (k4.w + a4.w) + scale * k4.w * b4.w;
            }
        }
        bool ok = (sm[t] == sm[s]);
        #pragma unroll
        for (int g = 0; g < GA; g++)
            satt[(g * Tt + t) * 33 + s] = ok ? acc[g] : -1e30f;
    }
    __syncthreads();

    int warp = tid >> 5, lane = tid & 31;
    for (int r = warp * 8; r < warp * 8 + 8; r++) {
        float v = satt[r * 33 + lane];
        float m = v;
        #pragma unroll
        for (int o = 16; o; o >>= 1) m = fmaxf(m, __shfl_xor_sync(0xffffffffu, m, o));
        float ev = expf(v - m);
        float ssum = ev;
        #pragma unroll
        for (int o = 16; o; o >>= 1) ssum += __shfl_xor_sync(0xffffffffu, ssum, o);
        satt[r * 33 + lane] = ev / ssum;
    }
    __syncthreads();

    const float* Rv = g_R + ((size_t)(2 * Bb + b) * (Tt * Tt)) * Cc + h * Fv;
    __nv_bfloat16* ob = g_attout_bf + ((size_t)(b * Dd + d0) * Tt) * Cc + h * Fv;
    #pragma unroll
    for (int i = 0; i < 4; i++) {
        int e = tid + 512 * i;
        int t = e >> 6, f = e & 63;
        const float* rv = Rv + (size_t)(t * Tt) * Cc + f;
        float acc[GA] = {0.f, 0.f, 0.f, 0.f};
        #pragma unroll
        for (int s = 0; s < Tt; s++) {
            float rvv = rv[(size_t)s * Cc];
            #pragma unroll
            for (int g = 0; g < GA; g++)
                acc[g] += satt[(g * Tt + t) * 33 + s] * (sv[(g * Tt + s) * QROW + f] + rvv);
        }
        #pragma unroll
        for (int g = 0; g < GA; g++)
            ob[((size_t)g * Tt + t) * Cc + f] = __float2bfloat16(acc[g]);
    }
}

// ---------------- final transpose [B,D,T,C] -> [B,D,C,T] ----------------
__global__ void transpose_out(float* __restrict__ out) {
    int bd = blockIdx.x, ct = blockIdx.y;
    __shared__ float s[32][33];
    int tx = threadIdx.x, ty = threadIdx.y;
    const float* yb = g_y + (size_t)bd * Tt * Cc;
    #pragma unroll
    for (int k = 0; k < 4; k++) {
        int t = ty + 8 * k;
        s[t][tx] = yb[t * Cc + ct * 32 + tx];
    }
    __syncthreads();
    float* ob = out + (size_t)bd * Cc * Tt;
    #pragma unroll
    for (int k = 0; k < 4; k++) {
        int c = ct * 32 + ty + 8 * k;
        ob[c * Tt + tx] = s[tx][ty + 8 * k];
    }
}

// ---------------- launch ----------------
extern "C" void kernel_launch(void* const* d_in, const int* in_sizes, int n_in,
                              void* d_out, int out_size) {
    const float* x      = (const float*)d_in[0];
    const float* temb   = (const float*)d_in[1];
    const int*   fi     = (const int*)d_in[2];
    const int*   amask  = (const int*)d_in[3];
    const float* norm_w = (const float*)d_in[4];
    const float* norm_b = (const float*)d_in[5];
    const float* qkv_w  = (const float*)d_in[6];
    const float* qkv_b  = (const float*)d_in[7];
    const float* proj_w = (const float*)d_in[8];
    const float* proj_b = (const float*)d_in[9];
    float* out = (float*)d_out;

    float *p_xt, *p_time, *p_R, *p_qkv, *p_y;
    __nv_bfloat16 *p_xtbf, *p_Ebf, *p_attbf, *p_wbf;
    cudaGetSymbolAddress((void**)&p_xt, g_xt);
    cudaGetSymbolAddress((void**)&p_xtbf, g_xt_bf);
    cudaGetSymbolAddress((void**)&p_time, g_time);
    cudaGetSymbolAddress((void**)&p_Ebf, g_E_bf);
    cudaGetSymbolAddress((void**)&p_R, g_R);
    cudaGetSymbolAddress((void**)&p_qkv, g_qkv);
    cudaGetSymbolAddress((void**)&p_attbf, g_attout_bf);
    cudaGetSymbolAddress((void**)&p_y, g_y);
    cudaGetSymbolAddress((void**)&p_wbf, g_wbf);

    cudaFuncSetAttribute(attn_kernel, cudaFuncAttributeMaxDynamicSharedMemorySize,
                         ATT_SMEM_BYTES);
    cudaFuncSetAttribute(gemm_bf, cudaFuncAttributeMaxDynamicSharedMemorySize,
                         GBF_SMEM);

    dim3 tb(32, 8);

    // 1-2. group norm (+ bf16 copy of xt)
    gn_stats<<<Bb * Dd, 256>>>(x);
    gn_norm_transpose<<<dim3(Bb * Dd, Cc / 32), tb>>>(x, norm_w, norm_b);

    // 3. weight conversion to bf16 (qkv | proj | q_out | k_out | v_out)
    cvt_w<<<dim3(768, 5), 256>>>(qkv_w, proj_w,
        (const float*)d_in[14], (const float*)d_in[20], (const float*)d_in[26]);

    // 4. QKV GEMM bf16: [32768, 512] @ [512, 1536]^T  (4th launch -> ncu target)
    gemm_bf<<<dim3((3 * Cc) / 128, (Bb * Dd * Tt) / 128, 1), 256, GBF_SMEM>>>(
        p_xtbf, 0, p_wbf, 0, qkv_b, qkv_b, qkv_b,
        nullptr, p_qkv, 0, Bb * Dd * Tt, 3 * Cc, Cc);

    // 5. time GEMMs (fp32 FFMA)
    time_gemm<<<dim3(8, 8, 3), 256>>>(temb,
        (const float*)d_in[12], (const float*)d_in[18], (const float*)d_in[24],
        (const float*)d_in[13], (const float*)d_in[19], (const float*)d_in[25]);

    // 6. emb + silu -> bf16 E
    emb_silu<<<dim3(Bb * Tt * Tt, 3), Cc>>>(
        fi,
        (const float*)d_in[10], (const float*)d_in[11],
        (const float*)d_in[16], (const float*)d_in[17],
        (const float*)d_in[22], (const float*)d_in[23]);

    // 7. RPE out GEMMs bf16, z=3: [2048, 512] @ [512, 512]^T
    gemm_bf<<<dim3(Cc / 128, (Bb * Tt * Tt) / 128, 3), 256, GBF_SMEM>>>(
        p_Ebf, (size_t)Bb * Tt * Tt * Cc,
        p_wbf + 1048576, 262144,
        (const float*)d_in[15], (const float*)d_in[21], (const float*)d_in[27],
        nullptr, p_R, (size_t)Bb * Tt * Tt * Cc,
        Bb * Tt * Tt, Cc, Cc);

    // 8. attention (writes bf16 attout)
    attn_kernel<<<Bb * Hh * (Dd / GA), 512, ATT_SMEM_BYTES>>>(amask);

    // 9. proj GEMM bf16 + residual (fp32 xt)
    gemm_bf<<<dim3(Cc / 128, (Bb * Dd * Tt) / 128, 1), 256, GBF_SMEM>>>(
        p_attbf, 0, p_wbf + 786432, 0, proj_b, proj_b, proj_b,
        p_xt, p_y, 0, Bb * Dd * Tt, Cc, Cc);

    // 10. output transpose
    transpose_out<<<dim3(Bb * Dd, Cc / 32), tb>>>(out);
}